// round 15
// baseline (speedup 1.0000x reference)
#include <cuda_runtime.h>

typedef unsigned int u32;

#define M_TOT   16384
#define HID     1024
#define INTERF  4096

// Activation (post-ReLU) fixed quantization scale: |inter| <= ~5.7 sigma, use 8.
#define S_ACT   (8.0f / 127.0f)
#define INV_ACT (127.0f / 8.0f)

// ---------------- device scratch (allocation-free: __device__ globals) ------
__device__ char  g_Xh [M_TOT * HID];
__device__ char  g_Xl [M_TOT * HID];
__device__ char  g_W1h[INTERF * HID];
__device__ char  g_W1l[INTERF * HID];
__device__ char  g_W2h[HID * INTERF];
__device__ char  g_W2l[HID * INTERF];
__device__ char  g_Ah [M_TOT * INTERF];
__device__ char  g_Al [M_TOT * INTERF];
__device__ float g_sX [M_TOT];
__device__ float g_sW1[INTERF];
__device__ float g_sW2[HID];

// ---------------- baseline-PTX helpers (no 'a'-gated features) --------------
__device__ __forceinline__ u32 smem_u32(const void* p) {
    return (u32)__cvta_generic_to_shared(p);
}

__device__ __forceinline__ void cp16(u32 dst, const void* src) {
    asm volatile("cp.async.cg.shared.global [%0], [%1], 16;\n" :: "r"(dst), "l"(src));
}
#define CP_COMMIT() asm volatile("cp.async.commit_group;\n" ::: "memory")
#define CP_WAIT(n)  asm volatile("cp.async.wait_group %0;\n" :: "n"(n) : "memory")

__device__ __forceinline__ void ldsm4(u32* r, u32 addr) {
    asm volatile("ldmatrix.sync.aligned.m8n8.x4.shared.b16 {%0,%1,%2,%3}, [%4];\n"
                 : "=r"(r[0]), "=r"(r[1]), "=r"(r[2]), "=r"(r[3]) : "r"(addr));
}

// int8 tensor-core MMA: m16n8k32, s32 accumulate (2x MAC/instr vs bf16 k16)
__device__ __forceinline__ void mma16832(int* d, const u32* a, u32 b0, u32 b1) {
    asm volatile(
        "mma.sync.aligned.m16n8k32.row.col.s32.s8.s8.s32 "
        "{%0,%1,%2,%3}, {%4,%5,%6,%7}, {%8,%9}, {%0,%1,%2,%3};\n"
        : "+r"(d[0]), "+r"(d[1]), "+r"(d[2]), "+r"(d[3])
        : "r"(a[0]), "r"(a[1]), "r"(a[2]), "r"(a[3]), "r"(b0), "r"(b1));
}

// ---------------- per-row quantization: f32 -> 2x int8 planes + scale -------
// v = s*(h + l/256),  s = rowmax/127,  |residual| <= s/512
__global__ void quant_rows_kernel(const float* __restrict__ in,
                                  char* __restrict__ h8, char* __restrict__ l8,
                                  float* __restrict__ scale, int C) {
    const int row = blockIdx.x;
    const int tid = threadIdx.x;
    const float* rp = in + (size_t)row * (size_t)C;
    const int c4 = C >> 2;

    float m = 0.0f;
    for (int i = tid; i < c4; i += 256) {
        float4 v = ((const float4*)rp)[i];
        m = fmaxf(m, fmaxf(fmaxf(fabsf(v.x), fabsf(v.y)),
                           fmaxf(fabsf(v.z), fabsf(v.w))));
    }
    #pragma unroll
    for (int o = 16; o; o >>= 1) m = fmaxf(m, __shfl_xor_sync(0xFFFFFFFFu, m, o));
    __shared__ float sm[8];
    if ((tid & 31) == 0) sm[tid >> 5] = m;
    __syncthreads();
    if (tid < 8) {
        float t = sm[tid];
        #pragma unroll
        for (int o = 4; o; o >>= 1) t = fmaxf(t, __shfl_xor_sync(0xFFu, t, o));
        if (tid == 0) sm[0] = t;
    }
    __syncthreads();
    const float mx = fmaxf(sm[0], 1e-20f);
    if (tid == 0) scale[row] = mx / 127.0f;
    const float inv = 127.0f / mx;

    char* hp = h8 + (size_t)row * (size_t)C;
    char* lp = l8 + (size_t)row * (size_t)C;
    for (int i = tid; i < c4; i += 256) {
        float4 v = ((const float4*)rp)[i];
        float q0 = v.x * inv, q1 = v.y * inv, q2 = v.z * inv, q3 = v.w * inv;
        float h0 = rintf(q0), h1 = rintf(q1), h2 = rintf(q2), h3 = rintf(q3);
        float l0 = fminf(fmaxf(rintf((q0 - h0) * 256.0f), -127.0f), 127.0f);
        float l1 = fminf(fmaxf(rintf((q1 - h1) * 256.0f), -127.0f), 127.0f);
        float l2 = fminf(fmaxf(rintf((q2 - h2) * 256.0f), -127.0f), 127.0f);
        float l3 = fminf(fmaxf(rintf((q3 - h3) * 256.0f), -127.0f), 127.0f);
        char4 hc = make_char4((char)(int)h0, (char)(int)h1, (char)(int)h2, (char)(int)h3);
        char4 lc = make_char4((char)(int)l0, (char)(int)l1, (char)(int)l2, (char)(int)l3);
        ((char4*)hp)[i] = hc;
        ((char4*)lp)[i] = lc;
    }
}

// ---------------- fused int8 GEMM: C = sa*sb*(Ah*Bh + (Al*Bh + Ah*Bl)/256) --
// CTA 128x128, 256 threads (8 warps: 2M x 4N, warp tile 64x32).
// K-chunk 64 int8 (64B rows, same byte geometry as 32xbf16), 3-stage cp.async,
// one __syncthreads per chunk. Rows padded to 80B -> conflict-free ldmatrix.
// MODE 0: +bias, relu, quantize to act planes (fixed S_ACT scale)  (layer 1)
// MODE 1: +bias, f32 store                                          (layer 2)

#define STAGES    3
#define ROW_B     80
#define TILE_B    (128 * ROW_B)             // 10240
#define OFF_AHI   0
#define OFF_ALO   (TILE_B)
#define OFF_BHI   (2 * TILE_B)
#define OFF_BLO   (3 * TILE_B)
#define STAGE_B   (4 * TILE_B)              // 40960
#define SMEM_BYTES (STAGES * STAGE_B)       // 122880

template <int MODE>
__global__ void __launch_bounds__(256, 1) ffn_gemm_i8_kernel(
    const char* __restrict__ Ah, const char* __restrict__ Al,
    const char* __restrict__ Bh, const char* __restrict__ Bl,
    const float* __restrict__ sa,      // per-row A scales (MODE 0); unused MODE 1
    const float* __restrict__ sb,      // per-row B scales
    const float* __restrict__ bias,
    char* __restrict__ outH, char* __restrict__ outL,   // MODE 0 outputs
    float* __restrict__ outF,                           // MODE 1 output
    int N, int K)
{
    extern __shared__ char smem[];
    const u32 sbase = smem_u32(smem);
    const int tid  = threadIdx.x;
    const int wid  = tid >> 5;
    const int lane = tid & 31;
    const int wm   = wid & 1;        // M: 2 warps x 64
    const int wn   = wid >> 1;       // N: 4 warps x 32
    const int n0   = blockIdx.x * 128;
    const int m0   = blockIdx.y * 128;

    // gmem loads: 128 rows x 64B per tile = 512 x 16B chunks; 2 per thread/tile
    const int rld = tid >> 2;              // row 0..63
    const int cld = tid & 3;               // 16B chunk within 64B row

    const int nchunks = K >> 6;            // 64 int8 per chunk

    auto load_chunk = [&](int s, int kc) {
        const int k0 = kc << 6;            // byte == element offset
        const u32 st = sbase + s * STAGE_B;
        const u32 so = (u32)(rld * ROW_B + cld * 16);
        const size_t koff = (size_t)(k0 + cld * 16);
        #pragma unroll
        for (int h = 0; h < 2; h++) {
            const int r = rld + h * 64;
            const u32 soh = so + (u32)(h * 64 * ROW_B);
            const size_t ga = (size_t)(m0 + r) * (size_t)K + koff;
            const size_t gb = (size_t)(n0 + r) * (size_t)K + koff;
            cp16(st + OFF_AHI + soh, Ah + ga);
            cp16(st + OFF_ALO + soh, Al + ga);
            cp16(st + OFF_BHI + soh, Bh + gb);
            cp16(st + OFF_BLO + soh, Bl + gb);
        }
    };

    int acch[4][4][4];   // hi*hi
    int accl[4][4][4];   // lo*hi + hi*lo (shared accumulator, weight 1/256)
    #pragma unroll
    for (int i = 0; i < 4; i++)
        #pragma unroll
        for (int j = 0; j < 4; j++)
            #pragma unroll
            for (int q = 0; q < 4; q++) { acch[i][j][q] = 0; accl[i][j][q] = 0; }

    #pragma unroll
    for (int s = 0; s < STAGES - 1; s++) {
        load_chunk(s, s);
        CP_COMMIT();
    }

    const int a_row = (lane & 15);
    const int colhi = (lane >> 4) * 16;     // byte half-select within 32B k-step
    const u32 aoff = (u32)((wm * 64 + a_row) * ROW_B);
    const u32 boff = (u32)((wn * 32 + a_row) * ROW_B);

    for (int kc = 0; kc < nchunks; kc++) {
        CP_WAIT(STAGES - 2);
        __syncthreads();

        {
            const int ld = kc + STAGES - 1;
            if (ld < nchunks) load_chunk(ld % STAGES, ld);
            CP_COMMIT();
        }

        const u32 st  = sbase + (kc % STAGES) * STAGE_B;
        const u32 sAh = st + OFF_AHI + aoff;
        const u32 sAl = st + OFF_ALO + aoff;
        const u32 sBh = st + OFF_BHI + boff;
        const u32 sBl = st + OFF_BLO + boff;

        #pragma unroll
        for (int ks = 0; ks < 2; ks++) {    // two k32 steps per 64B chunk
            const int cb = ks * 32 + colhi;
            u32 bh[2][4], bl[2][4];
            #pragma unroll
            for (int j2 = 0; j2 < 2; j2++) {
                const u32 ro = (u32)(j2 * 16 * ROW_B + cb);
                ldsm4(bh[j2], sBh + ro);
                ldsm4(bl[j2], sBl + ro);
            }
            u32 ah[4][4], al[4][4];
            #pragma unroll
            for (int mi = 0; mi < 4; mi++) {
                const u32 ro = (u32)((mi * 16) * ROW_B + cb);
                ldsm4(ah[mi], sAh + ro);
                ldsm4(al[mi], sAl + ro);
            }
            // combo-major: 16 independent IMMAs between accumulator reuse
            #pragma unroll
            for (int mi = 0; mi < 4; mi++)          // hi*hi
                #pragma unroll
                for (int nj = 0; nj < 4; nj++) {
                    const int j2 = nj >> 1, sl = nj & 1;
                    mma16832(acch[mi][nj], ah[mi], bh[j2][sl], bh[j2][sl + 2]);
                }
            #pragma unroll
            for (int mi = 0; mi < 4; mi++)          // lo*hi
                #pragma unroll
                for (int nj = 0; nj < 4; nj++) {
                    const int j2 = nj >> 1, sl = nj & 1;
                    mma16832(accl[mi][nj], al[mi], bh[j2][sl], bh[j2][sl + 2]);
                }
            #pragma unroll
            for (int mi = 0; mi < 4; mi++)          // hi*lo
                #pragma unroll
                for (int nj = 0; nj < 4; nj++) {
                    const int j2 = nj >> 1, sl = nj & 1;
                    mma16832(accl[mi][nj], ah[mi], bl[j2][sl], bl[j2][sl + 2]);
                }
        }
    }

    // ---------------- epilogue ----------------
    // acc[mi][nj]: d0=(r,c) d1=(r,c+1) d2=(r+8,c) d3=(r+8,c+1)
    const int er = lane >> 2;
    const int ec = (lane & 3) * 2;
    #pragma unroll
    for (int nj = 0; nj < 4; nj++) {
        const int col = n0 + wn * 32 + nj * 8 + ec;
        const float2 bz  = *(const float2*)(bias + col);
        const float2 sb2 = *(const float2*)(sb + col);
        #pragma unroll
        for (int mi = 0; mi < 4; mi++) {
            const int row = m0 + wm * 64 + mi * 16 + er;
            #pragma unroll
            for (int half = 0; half < 2; half++) {
                const int rr = row + half * 8;
                const float sav = (MODE == 0) ? __ldg(sa + rr) : S_ACT;
                const float s0 = sav * sb2.x;
                const float s1 = sav * sb2.y;
                float v0 = s0 * ((float)acch[mi][nj][half * 2 + 0]
                                 + (float)accl[mi][nj][half * 2 + 0] * (1.0f / 256.0f)) + bz.x;
                float v1 = s1 * ((float)acch[mi][nj][half * 2 + 1]
                                 + (float)accl[mi][nj][half * 2 + 1] * (1.0f / 256.0f)) + bz.y;
                if (MODE == 0) {
                    v0 = fmaxf(v0, 0.0f);
                    v1 = fmaxf(v1, 0.0f);
                    const float q0 = v0 * INV_ACT;
                    const float q1 = v1 * INV_ACT;
                    const float h0 = rintf(fminf(q0, 127.0f));
                    const float h1 = rintf(fminf(q1, 127.0f));
                    const float l0 = fminf(fmaxf(rintf((q0 - h0) * 256.0f), -127.0f), 127.0f);
                    const float l1 = fminf(fmaxf(rintf((q1 - h1) * 256.0f), -127.0f), 127.0f);
                    const size_t o = (size_t)rr * (size_t)N + col;
                    *(char2*)(outH + o) = make_char2((char)(int)h0, (char)(int)h1);
                    *(char2*)(outL + o) = make_char2((char)(int)l0, (char)(int)l1);
                } else {
                    const size_t o = (size_t)rr * (size_t)N + col;
                    *(float2*)(outF + o) = make_float2(v0, v1);
                }
            }
        }
    }
}

// ---------------- launch ----------------------------------------------------
extern "C" void kernel_launch(void* const* d_in, const int* in_sizes, int n_in,
                              void* d_out, int out_size) {
    const float* X  = (const float*)d_in[0];
    const float* W1 = (const float*)d_in[1];
    const float* b1 = (const float*)d_in[2];
    const float* W2 = (const float*)d_in[3];
    const float* b2 = (const float*)d_in[4];
    float* out = (float*)d_out;

    void *xh, *xl, *w1h, *w1l, *w2h, *w2l, *ah, *al, *sx, *sw1, *sw2;
    cudaGetSymbolAddress(&xh,  g_Xh);
    cudaGetSymbolAddress(&xl,  g_Xl);
    cudaGetSymbolAddress(&w1h, g_W1h);
    cudaGetSymbolAddress(&w1l, g_W1l);
    cudaGetSymbolAddress(&w2h, g_W2h);
    cudaGetSymbolAddress(&w2l, g_W2l);
    cudaGetSymbolAddress(&ah,  g_Ah);
    cudaGetSymbolAddress(&al,  g_Al);
    cudaGetSymbolAddress(&sx,  g_sX);
    cudaGetSymbolAddress(&sw1, g_sW1);
    cudaGetSymbolAddress(&sw2, g_sW2);

    cudaFuncSetAttribute(ffn_gemm_i8_kernel<0>, cudaFuncAttributeMaxDynamicSharedMemorySize, SMEM_BYTES);
    cudaFuncSetAttribute(ffn_gemm_i8_kernel<1>, cudaFuncAttributeMaxDynamicSharedMemorySize, SMEM_BYTES);

    // Quantize inputs (per-row scales)
    quant_rows_kernel<<<M_TOT,  256>>>(X,  (char*)xh,  (char*)xl,  (float*)sx,  HID);
    quant_rows_kernel<<<INTERF, 256>>>(W1, (char*)w1h, (char*)w1l, (float*)sw1, HID);
    quant_rows_kernel<<<HID,    256>>>(W2, (char*)w2h, (char*)w2l, (float*)sw2, INTERF);

    // Layer 1: inter = relu(X @ W1^T + b1) -> int8 act planes (fixed S_ACT)
    dim3 g1(INTERF / 128, M_TOT / 128);
    ffn_gemm_i8_kernel<0><<<g1, 256, SMEM_BYTES>>>(
        (const char*)xh, (const char*)xl,
        (const char*)w1h, (const char*)w1l,
        (const float*)sx, (const float*)sw1, b1,
        (char*)ah, (char*)al, (float*)nullptr,
        INTERF, HID);

    // Layer 2: out = act @ W2^T + b2 -> f32
    dim3 g2(HID / 128, M_TOT / 128);
    ffn_gemm_i8_kernel<1><<<g2, 256, SMEM_BYTES>>>(
        (const char*)ah, (const char*)al,
        (const char*)w2h, (const char*)w2l,
        (const float*)nullptr, (const float*)sw2, b2,
        (char*)nullptr, (char*)nullptr, out,
        HID, INTERF);
}

// round 16
// speedup vs baseline: 3.8514x; 3.8514x over previous
#include <cuda_runtime.h>
#include <cuda_fp16.h>

typedef unsigned int u32;

#define M_TOT   16384
#define HID     1024
#define INTERF  4096

// ---------------- device scratch (allocation-free: __device__ globals) ------
__device__ __half g_Xf [M_TOT * HID];      // X in fp16
__device__ __half g_W1f[INTERF * HID];     // W1 in fp16
__device__ __half g_W2f[HID * INTERF];     // W2 in fp16
__device__ __half g_Ah [M_TOT * INTERF];   // act hi plane
__device__ __half g_Al [M_TOT * INTERF];   // act lo plane (exact residual)

// ---------------- baseline-PTX helpers (no 'a'-gated features) --------------
__device__ __forceinline__ u32 smem_u32(const void* p) {
    return (u32)__cvta_generic_to_shared(p);
}

__device__ __forceinline__ void cp16(u32 dst, const void* src) {
    asm volatile("cp.async.cg.shared.global [%0], [%1], 16;\n" :: "r"(dst), "l"(src));
}
#define CP_COMMIT() asm volatile("cp.async.commit_group;\n" ::: "memory")
#define CP_WAIT(n)  asm volatile("cp.async.wait_group %0;\n" :: "n"(n) : "memory")

__device__ __forceinline__ void ldsm4(u32* r, u32 addr) {
    asm volatile("ldmatrix.sync.aligned.m8n8.x4.shared.b16 {%0,%1,%2,%3}, [%4];\n"
                 : "=r"(r[0]), "=r"(r[1]), "=r"(r[2]), "=r"(r[3]) : "r"(addr));
}

__device__ __forceinline__ void mma16816(float* d, const u32* a, u32 b0, u32 b1) {
    asm volatile(
        "mma.sync.aligned.m16n8k16.row.col.f32.f16.f16.f32 "
        "{%0,%1,%2,%3}, {%4,%5,%6,%7}, {%8,%9}, {%0,%1,%2,%3};\n"
        : "+f"(d[0]), "+f"(d[1]), "+f"(d[2]), "+f"(d[3])
        : "r"(a[0]), "r"(a[1]), "r"(a[2]), "r"(a[3]), "r"(b0), "r"(b1));
}

__device__ __forceinline__ u32 pack_h2(__half a, __half b) {
    __half2 h2 = __halves2half2(a, b);
    return *(u32*)&h2;
}

// ---------------- convert kernel: f32 -> fp16 --------------------------------
__global__ void cvt_f16_kernel(const float* __restrict__ in,
                               __half* __restrict__ out, int n4) {
    int i = blockIdx.x * blockDim.x + threadIdx.x;
    if (i >= n4) return;
    float4 v = ((const float4*)in)[i];
    u32 p0 = pack_h2(__float2half(v.x), __float2half(v.y));
    u32 p1 = pack_h2(__float2half(v.z), __float2half(v.w));
    ((uint2*)out)[i] = make_uint2(p0, p1);
}

// ---------------- fp16 GEMM -------------------------------------------------
// CTA 128x128, 256 threads (8 warps: 2M x 4N, warp tile 64x32).
// K-chunk 32 fp16 (64B rows), 4-stage cp.async pipeline, one barrier/chunk.
// Rows padded to 80B stride -> conflict-free ldmatrix.
// MODE 0 (layer 1): C = Xf16 @ W1f16^T        (+b1, relu, split -> Ah/Al)
// MODE 1 (layer 2): C = (Ah + Al) @ W2f16^T   (+b2, f32 store)  [2 combos]

#define STAGES    4
#define ROW_B     80
#define TILE_B    (128 * ROW_B)             // 10240

template <int MODE>
__global__ void __launch_bounds__(256, 1) ffn_f16_kernel(
    const __half* __restrict__ A0, const __half* __restrict__ A1,
    const __half* __restrict__ B,
    const float* __restrict__ bias,
    __half* __restrict__ outH, __half* __restrict__ outL,
    float* __restrict__ outF,
    int N, int K)
{
    constexpr int APL     = (MODE == 0) ? 1 : 2;   // A planes
    constexpr int STAGE_B = (APL + 1) * TILE_B;
    constexpr int OFF_A0  = 0;
    constexpr int OFF_A1  = TILE_B;                 // valid when APL==2
    constexpr int OFF_B   = APL * TILE_B;

    extern __shared__ char smem[];
    const u32 sbase = smem_u32(smem);
    const int tid  = threadIdx.x;
    const int wid  = tid >> 5;
    const int lane = tid & 31;
    const int wm   = wid & 1;        // M: 2 warps x 64
    const int wn   = wid >> 1;       // N: 4 warps x 32
    const int n0   = blockIdx.x * 128;
    const int m0   = blockIdx.y * 128;

    // gmem loads: per tile 128 rows x 64B = 512 x 16B; 2 chunks per thread
    const int rld = tid >> 2;              // row 0..63
    const int cld = tid & 3;               // 16B chunk within 64B row

    const int nchunks = K >> 5;            // 32 fp16 per chunk

    auto load_chunk = [&](int s, int kc) {
        const int k0 = kc << 5;
        const u32 st = sbase + s * STAGE_B;
        const u32 so = (u32)(rld * ROW_B + cld * 16);
        const size_t koff = (size_t)(k0 + cld * 8);
        #pragma unroll
        for (int h = 0; h < 2; h++) {
            const int r = rld + h * 64;
            const u32 soh = so + (u32)(h * 64 * ROW_B);
            const size_t ga = (size_t)(m0 + r) * (size_t)K + koff;
            const size_t gb = (size_t)(n0 + r) * (size_t)K + koff;
            cp16(st + OFF_A0 + soh, A0 + ga);
            if (APL == 2) cp16(st + OFF_A1 + soh, A1 + ga);
            cp16(st + OFF_B + soh, B + gb);
        }
    };

    float acc[4][4][4];
    #pragma unroll
    for (int i = 0; i < 4; i++)
        #pragma unroll
        for (int j = 0; j < 4; j++)
            #pragma unroll
            for (int q = 0; q < 4; q++) acc[i][j][q] = 0.0f;

    #pragma unroll
    for (int s = 0; s < STAGES - 1; s++) {
        if (s < nchunks) load_chunk(s, s);
        CP_COMMIT();
    }

    const int a_row = (lane & 15);
    const int colhi = (lane >> 4) * 16;     // byte half within 32B k16 step
    const u32 aoff = (u32)((wm * 64 + a_row) * ROW_B);
    const u32 boff = (u32)((wn * 32 + a_row) * ROW_B);

    for (int kc = 0; kc < nchunks; kc++) {
        CP_WAIT(STAGES - 2);
        __syncthreads();

        {   // prefetch chunk kc+STAGES-1 into slot freed last iteration
            const int ld = kc + STAGES - 1;
            if (ld < nchunks) load_chunk(ld % STAGES, ld);
            CP_COMMIT();
        }

        const u32 st  = sbase + (kc % STAGES) * STAGE_B;
        const u32 sA0 = st + OFF_A0 + aoff;
        const u32 sA1 = st + OFF_A1 + aoff;
        const u32 sB  = st + OFF_B  + boff;

        #pragma unroll
        for (int ks = 0; ks < 2; ks++) {
            const int cb = ks * 32 + colhi;
            u32 bh[2][4];
            #pragma unroll
            for (int j2 = 0; j2 < 2; j2++) {
                const u32 ro = (u32)(j2 * 16 * ROW_B + cb);
                ldsm4(bh[j2], sB + ro);
            }
            u32 a0[4][4], a1[4][4];
            #pragma unroll
            for (int mi = 0; mi < 4; mi++) {
                const u32 ro = (u32)((mi * 16) * ROW_B + cb);
                ldsm4(a0[mi], sA0 + ro);
                if (APL == 2) ldsm4(a1[mi], sA1 + ro);
            }
            #pragma unroll
            for (int mi = 0; mi < 4; mi++)
                #pragma unroll
                for (int nj = 0; nj < 4; nj++) {
                    const int j2 = nj >> 1, sl = nj & 1;
                    mma16816(acc[mi][nj], a0[mi], bh[j2][sl], bh[j2][sl + 2]);
                }
            if (APL == 2) {
                #pragma unroll
                for (int mi = 0; mi < 4; mi++)
                    #pragma unroll
                    for (int nj = 0; nj < 4; nj++) {
                        const int j2 = nj >> 1, sl = nj & 1;
                        mma16816(acc[mi][nj], a1[mi], bh[j2][sl], bh[j2][sl + 2]);
                    }
            }
        }
        // top-of-iteration barrier prevents WAR across iterations
    }

    // ---------------- epilogue ----------------
    // acc[mi][nj]: d0=(r,c) d1=(r,c+1) d2=(r+8,c) d3=(r+8,c+1)
    const int er = lane >> 2;
    const int ec = (lane & 3) * 2;
    #pragma unroll
    for (int nj = 0; nj < 4; nj++) {
        const int col = n0 + wn * 32 + nj * 8 + ec;
        const float2 bz = __ldg((const float2*)(bias + col));
        #pragma unroll
        for (int mi = 0; mi < 4; mi++) {
            const int row = m0 + wm * 64 + mi * 16 + er;
            #pragma unroll
            for (int half = 0; half < 2; half++) {
                const int rr = row + half * 8;
                float v0 = acc[mi][nj][half * 2 + 0] + bz.x;
                float v1 = acc[mi][nj][half * 2 + 1] + bz.y;
                const size_t o = (size_t)rr * (size_t)N + col;
                if (MODE == 0) {
                    v0 = fmaxf(v0, 0.0f);
                    v1 = fmaxf(v1, 0.0f);
                    __half h0 = __float2half(v0);
                    __half h1 = __float2half(v1);
                    __half l0 = __float2half(v0 - __half2float(h0));
                    __half l1 = __float2half(v1 - __half2float(h1));
                    *(u32*)(outH + o) = pack_h2(h0, h1);
                    *(u32*)(outL + o) = pack_h2(l0, l1);
                } else {
                    *(float2*)(outF + o) = make_float2(v0, v1);
                }
            }
        }
    }
}

// ---------------- launch ----------------------------------------------------
extern "C" void kernel_launch(void* const* d_in, const int* in_sizes, int n_in,
                              void* d_out, int out_size) {
    const float* X  = (const float*)d_in[0];
    const float* W1 = (const float*)d_in[1];
    const float* b1 = (const float*)d_in[2];
    const float* W2 = (const float*)d_in[3];
    const float* b2 = (const float*)d_in[4];
    float* out = (float*)d_out;

    void *xf, *w1f, *w2f, *ah, *al;
    cudaGetSymbolAddress(&xf,  g_Xf);
    cudaGetSymbolAddress(&w1f, g_W1f);
    cudaGetSymbolAddress(&w2f, g_W2f);
    cudaGetSymbolAddress(&ah,  g_Ah);
    cudaGetSymbolAddress(&al,  g_Al);

    constexpr int SMEM1 = STAGES * 2 * TILE_B;   // layer 1: A + B       (81920)
    constexpr int SMEM2 = STAGES * 3 * TILE_B;   // layer 2: Ah + Al + B (122880)
    cudaFuncSetAttribute(ffn_f16_kernel<0>, cudaFuncAttributeMaxDynamicSharedMemorySize, SMEM1);
    cudaFuncSetAttribute(ffn_f16_kernel<1>, cudaFuncAttributeMaxDynamicSharedMemorySize, SMEM2);

    // Converts: f32 -> fp16
    {
        int n4 = M_TOT * HID / 4;
        cvt_f16_kernel<<<(n4 + 255) / 256, 256>>>(X, (__half*)xf, n4);
    }
    {
        int n4 = INTERF * HID / 4;
        cvt_f16_kernel<<<(n4 + 255) / 256, 256>>>(W1, (__half*)w1f, n4);
    }
    {
        int n4 = HID * INTERF / 4;
        cvt_f16_kernel<<<(n4 + 255) / 256, 256>>>(W2, (__half*)w2f, n4);
    }

    // Layer 1 (1 combo): inter = relu(X @ W1^T + b1) -> fp16 hi/lo act planes
    dim3 g1(INTERF / 128, M_TOT / 128);
    ffn_f16_kernel<0><<<g1, 256, SMEM1>>>(
        (const __half*)xf, (const __half*)nullptr,
        (const __half*)w1f, b1,
        (__half*)ah, (__half*)al, (float*)nullptr,
        INTERF, HID);

    // Layer 2 (2 combos): out = (actH + actL) @ W2^T + b2 -> f32
    dim3 g2(HID / 128, M_TOT / 128);
    ffn_f16_kernel<1><<<g2, 256, SMEM2>>>(
        (const __half*)ah, (const __half*)al,
        (const __half*)w2f, b2,
        (__half*)nullptr, (__half*)nullptr, out,
        HID, INTERF);
}

// round 17
// speedup vs baseline: 6.1634x; 1.6003x over previous
#include <cuda_runtime.h>
#include <cuda_fp16.h>

typedef unsigned int u32;

#define M_TOT   16384
#define HID     1024
#define INTERF  4096

// ---------------- device scratch (allocation-free: __device__ globals) ------
__device__ __half g_Xf [M_TOT * HID];      // X in fp16
__device__ __half g_W1f[INTERF * HID];     // W1 in fp16
__device__ __half g_W2f[HID * INTERF];     // W2 in fp16
__device__ __half g_Af [M_TOT * INTERF];   // act in fp16 (single plane)

// ---------------- baseline-PTX helpers (no 'a'-gated features) --------------
__device__ __forceinline__ u32 smem_u32(const void* p) {
    return (u32)__cvta_generic_to_shared(p);
}

__device__ __forceinline__ void cp16(u32 dst, const void* src) {
    asm volatile("cp.async.cg.shared.global [%0], [%1], 16;\n" :: "r"(dst), "l"(src));
}
#define CP_COMMIT() asm volatile("cp.async.commit_group;\n" ::: "memory")
#define CP_WAIT(n)  asm volatile("cp.async.wait_group %0;\n" :: "n"(n) : "memory")

__device__ __forceinline__ void ldsm4(u32* r, u32 addr) {
    asm volatile("ldmatrix.sync.aligned.m8n8.x4.shared.b16 {%0,%1,%2,%3}, [%4];\n"
                 : "=r"(r[0]), "=r"(r[1]), "=r"(r[2]), "=r"(r[3]) : "r"(addr));
}

__device__ __forceinline__ void mma16816(float* d, const u32* a, u32 b0, u32 b1) {
    asm volatile(
        "mma.sync.aligned.m16n8k16.row.col.f32.f16.f16.f32 "
        "{%0,%1,%2,%3}, {%4,%5,%6,%7}, {%8,%9}, {%0,%1,%2,%3};\n"
        : "+f"(d[0]), "+f"(d[1]), "+f"(d[2]), "+f"(d[3])
        : "r"(a[0]), "r"(a[1]), "r"(a[2]), "r"(a[3]), "r"(b0), "r"(b1));
}

__device__ __forceinline__ u32 pack_h2(__half a, __half b) {
    __half2 h2 = __halves2half2(a, b);
    return *(u32*)&h2;
}

// ---------------- convert kernel: f32 -> fp16 --------------------------------
__global__ void cvt_f16_kernel(const float* __restrict__ in,
                               __half* __restrict__ out, int n4) {
    int i = blockIdx.x * blockDim.x + threadIdx.x;
    if (i >= n4) return;
    float4 v = ((const float4*)in)[i];
    u32 p0 = pack_h2(__float2half(v.x), __float2half(v.y));
    u32 p1 = pack_h2(__float2half(v.z), __float2half(v.w));
    ((uint2*)out)[i] = make_uint2(p0, p1);
}

// ---------------- fp16 GEMM (single combo) ----------------------------------
// CTA 128x128, 256 threads (8 warps: 2M x 4N, warp tile 64x32).
// K-chunk 32 fp16 (64B rows), 4-stage cp.async pipeline, one barrier/chunk.
// Rows padded to 80B stride -> conflict-free ldmatrix.
// MODE 0 (layer 1): C = X @ W1^T + b1, relu -> fp16 act
// MODE 1 (layer 2): C = A @ W2^T + b2      -> f32

#define STAGES    4
#define ROW_B     80
#define TILE_B    (128 * ROW_B)             // 10240
#define STAGE_B   (2 * TILE_B)              // 20480
#define SMEM_BYTES (STAGES * STAGE_B)       // 81920

template <int MODE>
__global__ void __launch_bounds__(256, 1) ffn_f16_kernel(
    const __half* __restrict__ A,
    const __half* __restrict__ B,
    const float* __restrict__ bias,
    __half* __restrict__ outH,
    float* __restrict__ outF,
    int N, int K)
{
    extern __shared__ char smem[];
    const u32 sbase = smem_u32(smem);
    const int tid  = threadIdx.x;
    const int wid  = tid >> 5;
    const int lane = tid & 31;
    const int wm   = wid & 1;        // M: 2 warps x 64
    const int wn   = wid >> 1;       // N: 4 warps x 32
    const int n0   = blockIdx.x * 128;
    const int m0   = blockIdx.y * 128;

    // gmem loads: per tile 128 rows x 64B = 512 x 16B; 2 chunks per thread
    const int rld = tid >> 2;              // row 0..63
    const int cld = tid & 3;               // 16B chunk within 64B row

    const int nchunks = K >> 5;            // 32 fp16 per chunk

    auto load_chunk = [&](int s, int kc) {
        const int k0 = kc << 5;
        const u32 st = sbase + s * STAGE_B;
        const u32 so = (u32)(rld * ROW_B + cld * 16);
        const size_t koff = (size_t)(k0 + cld * 8);
        #pragma unroll
        for (int h = 0; h < 2; h++) {
            const int r = rld + h * 64;
            const u32 soh = so + (u32)(h * 64 * ROW_B);
            const size_t ga = (size_t)(m0 + r) * (size_t)K + koff;
            const size_t gb = (size_t)(n0 + r) * (size_t)K + koff;
            cp16(st + soh, A + ga);
            cp16(st + TILE_B + soh, B + gb);
        }
    };

    float acc[4][4][4];
    #pragma unroll
    for (int i = 0; i < 4; i++)
        #pragma unroll
        for (int j = 0; j < 4; j++)
            #pragma unroll
            for (int q = 0; q < 4; q++) acc[i][j][q] = 0.0f;

    #pragma unroll
    for (int s = 0; s < STAGES - 1; s++) {
        if (s < nchunks) load_chunk(s, s);
        CP_COMMIT();
    }

    const int a_row = (lane & 15);
    const int colhi = (lane >> 4) * 16;     // byte half within 32B k16 step
    const u32 aoff = (u32)((wm * 64 + a_row) * ROW_B);
    const u32 boff = (u32)((wn * 32 + a_row) * ROW_B);

    for (int kc = 0; kc < nchunks; kc++) {
        CP_WAIT(STAGES - 2);
        __syncthreads();

        {   // prefetch chunk kc+STAGES-1 into slot freed last iteration
            const int ld = kc + STAGES - 1;
            if (ld < nchunks) load_chunk(ld % STAGES, ld);
            CP_COMMIT();
        }

        const u32 st = sbase + (kc % STAGES) * STAGE_B;
        const u32 sA = st + aoff;
        const u32 sB = st + TILE_B + boff;

        #pragma unroll
        for (int ks = 0; ks < 2; ks++) {
            const int cb = ks * 32 + colhi;
            u32 bh[2][4];
            #pragma unroll
            for (int j2 = 0; j2 < 2; j2++) {
                const u32 ro = (u32)(j2 * 16 * ROW_B + cb);
                ldsm4(bh[j2], sB + ro);
            }
            u32 ar[4][4];
            #pragma unroll
            for (int mi = 0; mi < 4; mi++) {
                const u32 ro = (u32)((mi * 16) * ROW_B + cb);
                ldsm4(ar[mi], sA + ro);
            }
            #pragma unroll
            for (int mi = 0; mi < 4; mi++)
                #pragma unroll
                for (int nj = 0; nj < 4; nj++) {
                    const int j2 = nj >> 1, sl = nj & 1;
                    mma16816(acc[mi][nj], ar[mi], bh[j2][sl], bh[j2][sl + 2]);
                }
        }
        // top-of-iteration barrier prevents WAR across iterations
    }

    // ---------------- epilogue ----------------
    // acc[mi][nj]: d0=(r,c) d1=(r,c+1) d2=(r+8,c) d3=(r+8,c+1)
    const int er = lane >> 2;
    const int ec = (lane & 3) * 2;
    #pragma unroll
    for (int nj = 0; nj < 4; nj++) {
        const int col = n0 + wn * 32 + nj * 8 + ec;
        const float2 bz = __ldg((const float2*)(bias + col));
        #pragma unroll
        for (int mi = 0; mi < 4; mi++) {
            const int row = m0 + wm * 64 + mi * 16 + er;
            #pragma unroll
            for (int half = 0; half < 2; half++) {
                const int rr = row + half * 8;
                float v0 = acc[mi][nj][half * 2 + 0] + bz.x;
                float v1 = acc[mi][nj][half * 2 + 1] + bz.y;
                const size_t o = (size_t)rr * (size_t)N + col;
                if (MODE == 0) {
                    v0 = fmaxf(v0, 0.0f);
                    v1 = fmaxf(v1, 0.0f);
                    *(u32*)(outH + o) = pack_h2(__float2half(v0), __float2half(v1));
                } else {
                    *(float2*)(outF + o) = make_float2(v0, v1);
                }
            }
        }
    }
}

// ---------------- launch ----------------------------------------------------
extern "C" void kernel_launch(void* const* d_in, const int* in_sizes, int n_in,
                              void* d_out, int out_size) {
    const float* X  = (const float*)d_in[0];
    const float* W1 = (const float*)d_in[1];
    const float* b1 = (const float*)d_in[2];
    const float* W2 = (const float*)d_in[3];
    const float* b2 = (const float*)d_in[4];
    float* out = (float*)d_out;

    void *xf, *w1f, *w2f, *af;
    cudaGetSymbolAddress(&xf,  g_Xf);
    cudaGetSymbolAddress(&w1f, g_W1f);
    cudaGetSymbolAddress(&w2f, g_W2f);
    cudaGetSymbolAddress(&af,  g_Af);

    cudaFuncSetAttribute(ffn_f16_kernel<0>, cudaFuncAttributeMaxDynamicSharedMemorySize, SMEM_BYTES);
    cudaFuncSetAttribute(ffn_f16_kernel<1>, cudaFuncAttributeMaxDynamicSharedMemorySize, SMEM_BYTES);

    // Converts: f32 -> fp16
    {
        int n4 = M_TOT * HID / 4;
        cvt_f16_kernel<<<(n4 + 255) / 256, 256>>>(X, (__half*)xf, n4);
    }
    {
        int n4 = INTERF * HID / 4;
        cvt_f16_kernel<<<(n4 + 255) / 256, 256>>>(W1, (__half*)w1f, n4);
    }
    {
        int n4 = HID * INTERF / 4;
        cvt_f16_kernel<<<(n4 + 255) / 256, 256>>>(W2, (__half*)w2f, n4);
    }

    // Layer 1: inter = relu(X @ W1^T + b1) -> fp16 act
    dim3 g1(INTERF / 128, M_TOT / 128);
    ffn_f16_kernel<0><<<g1, 256, SMEM_BYTES>>>(
        (const __half*)xf, (const __half*)w1f, b1,
        (__half*)af, (float*)nullptr,
        INTERF, HID);

    // Layer 2: out = act @ W2^T + b2 -> f32
    dim3 g2(HID / 128, M_TOT / 128);
    ffn_f16_kernel<1><<<g2, 256, SMEM_BYTES>>>(
        (const __half*)af, (const __half*)w2f, b2,
        (__half*)nullptr, out,
        HID, INTERF);
}